// round 16
// baseline (speedup 1.0000x reference)
#include <cuda_runtime.h>
#include <cuda_bf16.h>
#include <math.h>
#include <stdint.h>

#define NN   50000
#define EE   800000
#define ETOT 850000
#define HIDD 256
#define FFND 1024
#define MTILES ((NN + 127) / 128)   // 391

// ---------------- scratch (static device globals; no allocs) ----------------
__device__ float    g_xsrc[(size_t)NN * HIDD];
__device__ float    g_h   [(size_t)NN * HIDD];
__device__ float    g_agg [(size_t)NN * HIDD];
__device__ float    g_ssrc[NN * 16];   // [n][t][h]
__device__ float    g_sdst[NN * 16];
__device__ float    g_denom[NN * 8];
// bf16 split operands
__device__ __nv_bfloat16 g_xh[(size_t)NN * HIDD], g_xl[(size_t)NN * HIDD];
__device__ __nv_bfloat16 g_hh[(size_t)NN * HIDD], g_hl[(size_t)NN * HIDD];
__device__ __nv_bfloat16 g_mh[(size_t)NN * FFND], g_ml[(size_t)NN * FFND];
__device__ __nv_bfloat16 g_wsh[HIDD * HIDD], g_wsl[HIDD * HIDD];
__device__ __nv_bfloat16 g_w1h[FFND * HIDD], g_w1l[FFND * HIDD];
__device__ __nv_bfloat16 g_w2h[HIDD * FFND], g_w2l[HIDD * FFND];

// ---------------- small helpers ----------------
__device__ __forceinline__ void red_add_v4(float* p, float a, float b, float c, float d) {
    asm volatile("red.global.add.v4.f32 [%0], {%1,%2,%3,%4};"
                 :: "l"(p), "f"(a), "f"(b), "f"(c), "f"(d) : "memory");
}
__device__ __forceinline__ uint32_t smem_u32(const void* p) {
    uint32_t a;
    asm("{ .reg .u64 t; cvta.to.shared.u64 t, %1; cvt.u32.u64 %0, t; }" : "=r"(a) : "l"(p));
    return a;
}
__device__ __forceinline__ void ldsm4(uint32_t* r, uint32_t addr) {
    asm volatile("ldmatrix.sync.aligned.m8n8.x4.shared.b16 {%0,%1,%2,%3}, [%4];"
                 : "=r"(r[0]), "=r"(r[1]), "=r"(r[2]), "=r"(r[3]) : "r"(addr));
}
__device__ __forceinline__ void mma16816(float* c, const uint32_t* a, const uint32_t* b) {
    asm volatile(
        "mma.sync.aligned.m16n8k16.row.col.f32.bf16.bf16.f32 "
        "{%0,%1,%2,%3}, {%4,%5,%6,%7}, {%8,%9}, {%0,%1,%2,%3};"
        : "+f"(c[0]), "+f"(c[1]), "+f"(c[2]), "+f"(c[3])
        : "r"(a[0]), "r"(a[1]), "r"(a[2]), "r"(a[3]), "r"(b[0]), "r"(b[1]));
}
__device__ __forceinline__ void cp16(uint32_t dst, const void* src, int pred_bytes) {
    asm volatile("cp.async.cg.shared.global [%0], [%1], 16, %2;"
                 :: "r"(dst), "l"(src), "r"(pred_bytes) : "memory");
}

// SMEM stage layout: Ah(128x32 bf16, 80B pitch)=10240, Al, Bh, Bl -> 40960 per stage, x2
#define ROWPITCH 80
#define MAT_BYTES 10240
#define STAGE_BYTES 40960
#define GEMM_SMEM (2 * STAGE_BYTES)

// ---------------- tensor-core GEMM (mma.sync bf16, 3-pass split) ----------------
// EPI: 0 f32 store + fused src att dots; 1 bias+gelu -> bf16 hi/lo; 2 bias -> f32
template<int EPI>
__global__ void __launch_bounds__(256, 2) gemm_tc(
    const __nv_bfloat16* __restrict__ Ah, const __nv_bfloat16* __restrict__ Al,
    const __nv_bfloat16* __restrict__ Bh, const __nv_bfloat16* __restrict__ Bl,
    float* __restrict__ Cf, __nv_bfloat16* __restrict__ Ch, __nv_bfloat16* __restrict__ Cl,
    const float* __restrict__ bias, const float* __restrict__ att, float* __restrict__ sd,
    int M, int Nd, int Kt)
{
    extern __shared__ __align__(128) char smem[];
    const uint32_t sb = smem_u32(smem);
    const int tid = threadIdx.x, wid = tid >> 5, lane = tid & 31;
    const int bm = blockIdx.y * 128, bn = blockIdx.x * 128;
    const int wm = (wid & 1) * 64, wn = (wid >> 1) * 32;

    float acc[4][4][4];
#pragma unroll
    for (int a = 0; a < 4; a++)
#pragma unroll
        for (int b = 0; b < 4; b++)
#pragma unroll
            for (int q = 0; q < 4; q++) acc[a][b][q] = 0.f;

    const int NC = Kt >> 5;

    auto issue_stage = [&](int c) {
        const int k0 = c << 5;
        const uint32_t stb = sb + (c & 1) * STAGE_BYTES;
#pragma unroll
        for (int j = 0; j < 8; j++) {
            int i = tid + (j << 8);
            int mt = i >> 9;            // 0 Ah, 1 Al, 2 Bh, 3 Bl
            int rem = i & 511;
            int row = rem >> 2, ch = rem & 3;
            uint32_t dst = stb + mt * MAT_BYTES + row * ROWPITCH + ch * 16;
            const __nv_bfloat16* src;
            int pb = 16;
            if (mt == 0) {
                int gm = bm + row;
                if (gm >= M) { gm = 0; pb = 0; }
                src = Ah + (size_t)gm * Kt + k0 + ch * 8;
            } else if (mt == 1) {
                int gm = bm + row;
                if (gm >= M) { gm = 0; pb = 0; }
                src = Al + (size_t)gm * Kt + k0 + ch * 8;
            } else if (mt == 2) {
                src = Bh + (size_t)(bn + row) * Kt + k0 + ch * 8;
            } else {
                src = Bl + (size_t)(bn + row) * Kt + k0 + ch * 8;
            }
            cp16(dst, src, pb);
        }
        asm volatile("cp.async.commit_group;" ::: "memory");
    };

    issue_stage(0);
    for (int c = 0; c < NC; c++) {
        if (c + 1 < NC) {
            issue_stage(c + 1);
            asm volatile("cp.async.wait_group 1;" ::: "memory");
        } else {
            asm volatile("cp.async.wait_group 0;" ::: "memory");
        }
        __syncthreads();
        const uint32_t stb = sb + (c & 1) * STAGE_BYTES;
#pragma unroll
        for (int kk = 0; kk < 2; kk++) {
            uint32_t bH[2][4], bL[2][4];
            const int brow = wn + (lane & 7) + ((lane >> 4) << 3);
            const int bcol = kk * 32 + ((lane >> 3) & 1) * 16;
#pragma unroll
            for (int p = 0; p < 2; p++) {
                uint32_t bd = stb + 2 * MAT_BYTES + (brow + p * 16) * ROWPITCH + bcol;
                ldsm4(bH[p], bd);
                ldsm4(bL[p], bd + MAT_BYTES);
            }
            const int arow = wm + (lane & 15);
            const int acol = kk * 32 + (lane >> 4) * 16;
            uint32_t aH[4][4], aL[4][4];
#pragma unroll
            for (int tm = 0; tm < 4; tm++) {
                uint32_t ad = stb + (arow + tm * 16) * ROWPITCH + acol;
                ldsm4(aH[tm], ad);
                ldsm4(aL[tm], ad + MAT_BYTES);
            }
            // three independent sweeps: consecutive HMMAs hit different accumulators
#pragma unroll
            for (int tm = 0; tm < 4; tm++)
#pragma unroll
                for (int tn = 0; tn < 4; tn++)
                    mma16816(acc[tm][tn], aH[tm], &bH[tn >> 1][(tn & 1) * 2]);
#pragma unroll
            for (int tm = 0; tm < 4; tm++)
#pragma unroll
                for (int tn = 0; tn < 4; tn++)
                    mma16816(acc[tm][tn], aH[tm], &bL[tn >> 1][(tn & 1) * 2]);
#pragma unroll
            for (int tm = 0; tm < 4; tm++)
#pragma unroll
                for (int tn = 0; tn < 4; tn++)
                    mma16816(acc[tm][tn], aL[tm], &bH[tn >> 1][(tn & 1) * 2]);
        }
        __syncthreads();
    }

    const int r0 = lane >> 2, c0 = (lane & 3) * 2;

    // fused src att dots (EPI 0): this warp's 32 cols = one head
    if (EPI == 0) {
        const int h = ((bn + wn) >> 5) & 7;
        const float* at0 = att + h * 32;         // t = 0
        const float* at1 = att + 256 + h * 32;   // t = 1
        float dt0[8], dt1[8];
#pragma unroll
        for (int q = 0; q < 8; q++) { dt0[q] = 0.f; dt1[q] = 0.f; }
#pragma unroll
        for (int tn = 0; tn < 4; tn++)
#pragma unroll
            for (int j = 0; j < 2; j++) {
                int cidx = tn * 8 + c0 + j;
                float a0 = at0[cidx], a1 = at1[cidx];
#pragma unroll
                for (int tm = 0; tm < 4; tm++)
#pragma unroll
                    for (int hf = 0; hf < 2; hf++) {
                        float v = acc[tm][tn][hf * 2 + j];
                        dt0[tm * 2 + hf] += v * a0;
                        dt1[tm * 2 + hf] += v * a1;
                    }
            }
#pragma unroll
        for (int q = 0; q < 8; q++) {
            dt0[q] += __shfl_xor_sync(0xffffffffu, dt0[q], 1);
            dt0[q] += __shfl_xor_sync(0xffffffffu, dt0[q], 2);
            dt1[q] += __shfl_xor_sync(0xffffffffu, dt1[q], 1);
            dt1[q] += __shfl_xor_sync(0xffffffffu, dt1[q], 2);
        }
        if ((lane & 3) == 0) {
#pragma unroll
            for (int tm = 0; tm < 4; tm++)
#pragma unroll
                for (int hf = 0; hf < 2; hf++) {
                    int m = bm + wm + tm * 16 + hf * 8 + r0;
                    if (m < M) {
                        sd[m * 16 + h]     = dt0[tm * 2 + hf];
                        sd[m * 16 + 8 + h] = dt1[tm * 2 + hf];
                    }
                }
        }
    }

    // epilogue stores
#pragma unroll
    for (int tm = 0; tm < 4; tm++) {
        const int mbase = bm + wm + tm * 16 + r0;
#pragma unroll
        for (int tn = 0; tn < 4; tn++) {
            const int n0 = bn + wn + tn * 8 + c0;
#pragma unroll
            for (int hf = 0; hf < 2; hf++) {
                const int m = mbase + hf * 8;
                if (m >= M) continue;
                float v0 = acc[tm][tn][hf * 2];
                float v1 = acc[tm][tn][hf * 2 + 1];
                if (EPI == 0) {
                    *(float2*)(Cf + (size_t)m * Nd + n0) = make_float2(v0, v1);
                } else if (EPI == 2) {
                    v0 += bias[n0]; v1 += bias[n0 + 1];
                    *(float2*)(Cf + (size_t)m * Nd + n0) = make_float2(v0, v1);
                } else {
                    v0 += bias[n0]; v1 += bias[n0 + 1];
                    v0 = 0.5f * v0 * (1.f + erff(v0 * 0.70710678118654752f));
                    v1 = 0.5f * v1 * (1.f + erff(v1 * 0.70710678118654752f));
                    __nv_bfloat16 h0 = __float2bfloat16(v0);
                    __nv_bfloat16 h1 = __float2bfloat16(v1);
                    __nv_bfloat162 hp; hp.x = h0; hp.y = h1;
                    __nv_bfloat162 lp;
                    lp.x = __float2bfloat16(v0 - __bfloat162float(h0));
                    lp.y = __float2bfloat16(v1 - __bfloat162float(h1));
                    *(__nv_bfloat162*)(Ch + (size_t)m * Nd + n0) = hp;
                    *(__nv_bfloat162*)(Cl + (size_t)m * Nd + n0) = lp;
                }
            }
        }
    }
}

// ---------------- dst att dots (V built in-CTA; src dots fused in gemm0) -------
__global__ void __launch_bounds__(256) dots_kernel(const float* __restrict__ x,
                                                   const float* __restrict__ Wdst,
                                                   const float* __restrict__ att_dst) {
    __shared__ float sVt[256][16];   // Vdst^T — 16KB
    int tid = threadIdx.x;
    {
        float a16[16];
#pragma unroll
        for (int q = 0; q < 16; q++) a16[q] = 0.f;
        for (int c = 0; c < 32; c++) {
#pragma unroll
            for (int h = 0; h < 8; h++) {
                float wv = Wdst[(h * 32 + c) * 256 + tid];
                a16[h]     += wv * __ldg(&att_dst[h * 32 + c]);
                a16[8 + h] += wv * __ldg(&att_dst[(8 + h) * 32 + c]);
            }
        }
#pragma unroll
        for (int q = 0; q < 16; q++) sVt[tid][q] = a16[q];
    }
    __syncthreads();
    int lane = tid & 31;
    int half = lane >> 4;
    int j = lane & 15;
    int gw = (blockIdx.x * 256 + tid) >> 5;
    int nw = (gridDim.x * 256) >> 5;
    for (int nb = gw * 8; nb < NN; nb += nw * 8) {
        int m0 = nb + half * 4;
        int m1 = m0 + 1, m2 = m0 + 2, m3 = m0 + 3;
        bool ok0 = m0 < NN, ok1 = m1 < NN, ok2 = m2 < NN, ok3 = m3 < NN;
        const float4* x0 = (const float4*)&x[(size_t)(ok0 ? m0 : 0) * HIDD];
        const float4* x1 = (const float4*)&x[(size_t)(ok1 ? m1 : 0) * HIDD];
        const float4* x2 = (const float4*)&x[(size_t)(ok2 ? m2 : 0) * HIDD];
        const float4* x3 = (const float4*)&x[(size_t)(ok3 ? m3 : 0) * HIDD];
        float a0 = 0.f, a1 = 0.f, a2 = 0.f, a3 = 0.f;
#pragma unroll 2
        for (int k4 = 0; k4 < 64; k4++) {
            float s0 = sVt[k4 * 4 + 0][j];
            float s1 = sVt[k4 * 4 + 1][j];
            float s2 = sVt[k4 * 4 + 2][j];
            float s3 = sVt[k4 * 4 + 3][j];
            float4 v;
            v = x0[k4]; a0 += v.x * s0 + v.y * s1 + v.z * s2 + v.w * s3;
            v = x1[k4]; a1 += v.x * s0 + v.y * s1 + v.z * s2 + v.w * s3;
            v = x2[k4]; a2 += v.x * s0 + v.y * s1 + v.z * s2 + v.w * s3;
            v = x3[k4]; a3 += v.x * s0 + v.y * s1 + v.z * s2 + v.w * s3;
        }
        if (ok0) g_sdst[m0 * 16 + j] = a0;
        if (ok1) g_sdst[m1 * 16 + j] = a1;
        if (ok2) g_sdst[m2 * 16 + j] = a2;
        if (ok3) g_sdst[m3 * 16 + j] = a3;
    }
}

// ---------------- prep: bf16 splits + zero agg/denom (fused) ----------------
#define SPLIT_X_N4   (NN * HIDD / 4)
#define SPLIT_WS_N4  (HIDD * HIDD / 4)
#define SPLIT_W1_N4  (FFND * HIDD / 4)
#define SPLIT_W2_N4  (HIDD * FFND / 4)
#define SPLIT_TOTAL  (SPLIT_X_N4 + SPLIT_WS_N4 + SPLIT_W1_N4 + SPLIT_W2_N4)

__global__ void prep_kernel(const float* __restrict__ x, const float* __restrict__ Wsrc,
                            const float* __restrict__ W1, const float* __restrict__ W2) {
    int i = blockIdx.x * blockDim.x + threadIdx.x;
    if (i >= SPLIT_TOTAL) return;
    if (i < SPLIT_X_N4)
        *(float4*)(g_agg + (size_t)i * 4) = make_float4(0.f, 0.f, 0.f, 0.f);
    if (i < NN * 2)
        *(float4*)(g_denom + (size_t)i * 4) = make_float4(0.f, 0.f, 0.f, 0.f);
    const float* in; __nv_bfloat16 *hi, *lo; int off;
    if (i < SPLIT_X_N4) {
        in = x; hi = g_xh; lo = g_xl; off = i;
    } else if (i < SPLIT_X_N4 + SPLIT_WS_N4) {
        in = Wsrc; hi = g_wsh; lo = g_wsl; off = i - SPLIT_X_N4;
    } else if (i < SPLIT_X_N4 + SPLIT_WS_N4 + SPLIT_W1_N4) {
        in = W1; hi = g_w1h; lo = g_w1l; off = i - SPLIT_X_N4 - SPLIT_WS_N4;
    } else {
        in = W2; hi = g_w2h; lo = g_w2l; off = i - SPLIT_X_N4 - SPLIT_WS_N4 - SPLIT_W1_N4;
    }
    float4 v = *(const float4*)(in + (size_t)off * 4);
    __nv_bfloat16 h0 = __float2bfloat16(v.x), h1 = __float2bfloat16(v.y);
    __nv_bfloat16 h2 = __float2bfloat16(v.z), h3 = __float2bfloat16(v.w);
    __nv_bfloat162 hp0; hp0.x = h0; hp0.y = h1;
    __nv_bfloat162 hp1; hp1.x = h2; hp1.y = h3;
    __nv_bfloat162 lp0, lp1;
    lp0.x = __float2bfloat16(v.x - __bfloat162float(h0));
    lp0.y = __float2bfloat16(v.y - __bfloat162float(h1));
    lp1.x = __float2bfloat16(v.z - __bfloat162float(h2));
    lp1.y = __float2bfloat16(v.w - __bfloat162float(h3));
    *(__nv_bfloat162*)(hi + (size_t)off * 4)     = hp0;
    *(__nv_bfloat162*)(hi + (size_t)off * 4 + 2) = hp1;
    *(__nv_bfloat162*)(lo + (size_t)off * 4)     = lp0;
    *(__nv_bfloat162*)(lo + (size_t)off * 4 + 2) = lp1;
}

// ---------------- fused edge pass: alpha -> leaky -> exp -> denom + scatter ----------
__global__ void __launch_bounds__(256) edge_fused(const int* __restrict__ ei,
                                                  const int* __restrict__ et,
                                                  const float* __restrict__ ew) {
    int e = (blockIdx.x * blockDim.x + threadIdx.x) >> 5;
    int lane = threadIdx.x & 31;
    if (e >= ETOT) return;
    int s, d, t; float w;
    if (e < EE) { s = ei[e]; d = ei[EE + e]; t = et[e]; w = ew[e]; }
    else        { s = d = e - EE; t = 0; w = 1.f; }
    float cv = 0.f;
    if (lane < 8) {
        float a = g_ssrc[s * 16 + t * 8 + lane] + g_sdst[d * 16 + t * 8 + lane];
        a = (a >= 0.f) ? a : 0.2f * a;
        float p = __expf(a);
        atomicAdd(&g_denom[d * 8 + lane], p);
        cv = p * w;
    }
    float c1 = __shfl_sync(0xffffffffu, cv, lane >> 3);        // heads 0..3
    float c2 = __shfl_sync(0xffffffffu, cv, 4 + (lane >> 3));  // heads 4..7
    const float4* xs = (const float4*)&g_xsrc[(size_t)s * HIDD];
    float4 v1 = xs[lane];
    float4 v2 = xs[32 + lane];
    float* op = &g_agg[(size_t)d * HIDD];
    red_add_v4(op + lane * 4,       v1.x * c1, v1.y * c1, v1.z * c1, v1.w * c1);
    red_add_v4(op + 128 + lane * 4, v2.x * c2, v2.y * c2, v2.z * c2, v2.w * c2);
}

// ---------------- LayerNorm: out = LN(a[/denom] + b + colbias?), optional bf16 split ----
__global__ void ln_kernel(const float* __restrict__ a, const float* __restrict__ b,
                          const float* __restrict__ colbias, const float* __restrict__ denom,
                          const float* __restrict__ g, const float* __restrict__ beta,
                          float* __restrict__ out,
                          __nv_bfloat16* __restrict__ ohi, __nv_bfloat16* __restrict__ olo) {
    int row = (blockIdx.x * blockDim.x + threadIdx.x) >> 5;
    int lane = threadIdx.x & 31;
    if (row >= NN) return;
    size_t base = (size_t)row * HIDD;
    float4 a0 = *(const float4*)&a[base + lane * 4];
    float4 a1 = *(const float4*)&a[base + 128 + lane * 4];
    float4 b0 = *(const float4*)&b[base + lane * 4];
    float4 b1 = *(const float4*)&b[base + 128 + lane * 4];
    if (denom) {
        float r0 = __frcp_rn(denom[row * 8 + (lane >> 3)]);
        float r1 = __frcp_rn(denom[row * 8 + 4 + (lane >> 3)]);
        a0.x *= r0; a0.y *= r0; a0.z *= r0; a0.w *= r0;
        a1.x *= r1; a1.y *= r1; a1.z *= r1; a1.w *= r1;
    }
    float v[8] = { a0.x + b0.x, a0.y + b0.y, a0.z + b0.z, a0.w + b0.w,
                   a1.x + b1.x, a1.y + b1.y, a1.z + b1.z, a1.w + b1.w };
    if (colbias) {
        float4 c0 = *(const float4*)&colbias[lane * 4];
        float4 c1 = *(const float4*)&colbias[128 + lane * 4];
        v[0] += c0.x; v[1] += c0.y; v[2] += c0.z; v[3] += c0.w;
        v[4] += c1.x; v[5] += c1.y; v[6] += c1.z; v[7] += c1.w;
    }
    float s = 0.f, s2 = 0.f;
#pragma unroll
    for (int q = 0; q < 8; q++) { s += v[q]; s2 += v[q] * v[q]; }
#pragma unroll
    for (int off = 16; off; off >>= 1) {
        s  += __shfl_xor_sync(0xffffffffu, s, off);
        s2 += __shfl_xor_sync(0xffffffffu, s2, off);
    }
    float mu = s * (1.f / 256.f);
    float var = s2 * (1.f / 256.f) - mu * mu;
    float r = rsqrtf(var + 1e-5f);
    float4 g0 = *(const float4*)&g[lane * 4];
    float4 g1 = *(const float4*)&g[128 + lane * 4];
    float4 e0 = *(const float4*)&beta[lane * 4];
    float4 e1 = *(const float4*)&beta[128 + lane * 4];
    float o[8];
    o[0] = (v[0] - mu) * r * g0.x + e0.x; o[1] = (v[1] - mu) * r * g0.y + e0.y;
    o[2] = (v[2] - mu) * r * g0.z + e0.z; o[3] = (v[3] - mu) * r * g0.w + e0.w;
    o[4] = (v[4] - mu) * r * g1.x + e1.x; o[5] = (v[5] - mu) * r * g1.y + e1.y;
    o[6] = (v[6] - mu) * r * g1.z + e1.z; o[7] = (v[7] - mu) * r * g1.w + e1.w;
    *(float4*)&out[base + lane * 4]       = make_float4(o[0], o[1], o[2], o[3]);
    *(float4*)&out[base + 128 + lane * 4] = make_float4(o[4], o[5], o[6], o[7]);
    if (ohi) {
#pragma unroll
        for (int q = 0; q < 8; q += 2) {
            int col = (q < 4) ? (lane * 4 + q) : (128 + lane * 4 + q - 4);
            __nv_bfloat16 h0 = __float2bfloat16(o[q]);
            __nv_bfloat16 h1 = __float2bfloat16(o[q + 1]);
            __nv_bfloat162 hp; hp.x = h0; hp.y = h1;
            __nv_bfloat162 lp;
            lp.x = __float2bfloat16(o[q] - __bfloat162float(h0));
            lp.y = __float2bfloat16(o[q + 1] - __bfloat162float(h1));
            *(__nv_bfloat162*)(ohi + base + col) = hp;
            *(__nv_bfloat162*)(olo + base + col) = lp;
        }
    }
}

// ---------------- launch ----------------
extern "C" void kernel_launch(void* const* d_in, const int* in_sizes, int n_in,
                              void* d_out, int out_size) {
    const float* x       = (const float*)d_in[0];
    const int*   ei      = (const int*)  d_in[1];
    const int*   et      = (const int*)  d_in[2];
    const float* ew      = (const float*)d_in[3];
    const float* Wsrc    = (const float*)d_in[4];
    const float* Wdst    = (const float*)d_in[5];
    const float* att_src = (const float*)d_in[6];
    const float* att_dst = (const float*)d_in[7];
    const float* bias    = (const float*)d_in[8];
    const float* ln1g    = (const float*)d_in[9];
    const float* ln1b    = (const float*)d_in[10];
    const float* ln2g    = (const float*)d_in[11];
    const float* ln2b    = (const float*)d_in[12];
    const float* W1      = (const float*)d_in[13];
    const float* b1      = (const float*)d_in[14];
    const float* W2      = (const float*)d_in[15];
    const float* b2      = (const float*)d_in[16];
    float* out = (float*)d_out;

    float *p_xsrc, *p_h, *p_agg, *p_denom, *p_ssrc;
    cudaGetSymbolAddress((void**)&p_xsrc, g_xsrc);
    cudaGetSymbolAddress((void**)&p_h,    g_h);
    cudaGetSymbolAddress((void**)&p_agg,  g_agg);
    cudaGetSymbolAddress((void**)&p_denom, g_denom);
    cudaGetSymbolAddress((void**)&p_ssrc, g_ssrc);
    __nv_bfloat16 *p_xh, *p_xl, *p_hh, *p_hl, *p_mh, *p_ml;
    __nv_bfloat16 *p_wsh, *p_wsl, *p_w1h, *p_w1l, *p_w2h, *p_w2l;
    cudaGetSymbolAddress((void**)&p_xh, g_xh);   cudaGetSymbolAddress((void**)&p_xl, g_xl);
    cudaGetSymbolAddress((void**)&p_hh, g_hh);   cudaGetSymbolAddress((void**)&p_hl, g_hl);
    cudaGetSymbolAddress((void**)&p_mh, g_mh);   cudaGetSymbolAddress((void**)&p_ml, g_ml);
    cudaGetSymbolAddress((void**)&p_wsh, g_wsh); cudaGetSymbolAddress((void**)&p_wsl, g_wsl);
    cudaGetSymbolAddress((void**)&p_w1h, g_w1h); cudaGetSymbolAddress((void**)&p_w1l, g_w1l);
    cudaGetSymbolAddress((void**)&p_w2h, g_w2h); cudaGetSymbolAddress((void**)&p_w2l, g_w2l);

    cudaFuncSetAttribute(gemm_tc<0>, cudaFuncAttributeMaxDynamicSharedMemorySize, GEMM_SMEM);
    cudaFuncSetAttribute(gemm_tc<1>, cudaFuncAttributeMaxDynamicSharedMemorySize, GEMM_SMEM);
    cudaFuncSetAttribute(gemm_tc<2>, cudaFuncAttributeMaxDynamicSharedMemorySize, GEMM_SMEM);

    const int TPB = 256;
    prep_kernel<<<(SPLIT_TOTAL + TPB - 1) / TPB, TPB>>>(x, Wsrc, W1, W2);     // 1
    dots_kernel<<<296, 256>>>(x, Wdst, att_dst);                              // 2
    gemm_tc<0><<<dim3(HIDD / 128, MTILES), 256, GEMM_SMEM>>>(                 // 3
        p_xh, p_xl, p_wsh, p_wsl, p_xsrc, nullptr, nullptr, nullptr,
        att_src, p_ssrc, NN, HIDD, HIDD);
    edge_fused<<<((size_t)ETOT * 32 + TPB - 1) / TPB, TPB>>>(ei, et, ew);     // 4

    ln_kernel<<<(NN * 32 + TPB - 1) / TPB, TPB>>>(p_agg, x, bias, p_denom,
                                                  ln1g, ln1b, p_h, p_hh, p_hl);

    gemm_tc<1><<<dim3(FFND / 128, MTILES), 256, GEMM_SMEM>>>(
        p_hh, p_hl, p_w1h, p_w1l, nullptr, p_mh, p_ml, b1, nullptr, nullptr,
        NN, FFND, HIDD);
    gemm_tc<2><<<dim3(HIDD / 128, MTILES), 256, GEMM_SMEM>>>(
        p_mh, p_ml, p_w2h, p_w2l, p_agg, nullptr, nullptr, b2, nullptr, nullptr,
        NN, HIDD, FFND);

    ln_kernel<<<(NN * 32 + TPB - 1) / TPB, TPB>>>(p_agg, p_h, nullptr, nullptr,
                                                  ln2g, ln2b, out, nullptr, nullptr);
}

// round 17
// speedup vs baseline: 1.2296x; 1.2296x over previous
#include <cuda_runtime.h>
#include <cuda_fp16.h>
#include <math.h>
#include <stdint.h>

#define NN   50000
#define EE   800000
#define ETOT 850000
#define HIDD 256
#define FFND 1024
#define MTILES ((NN + 127) / 128)   // 391

// ---------------- scratch (static device globals; no allocs) ----------------
__device__ float    g_xsrc[(size_t)NN * HIDD];
__device__ float    g_h   [(size_t)NN * HIDD];
__device__ float    g_agg [(size_t)NN * HIDD];
__device__ float    g_ssrc[NN * 16];   // [n][t][h]
__device__ float    g_sdst[NN * 16];
__device__ float    g_denom[NN * 8];
// fp16 operands: activations single, weights hi/lo split
__device__ __half g_xa[(size_t)NN * HIDD];
__device__ __half g_ha[(size_t)NN * HIDD];
__device__ __half g_ma[(size_t)NN * FFND];
__device__ __half g_wsh[HIDD * HIDD], g_wsl[HIDD * HIDD];
__device__ __half g_w1h[FFND * HIDD], g_w1l[FFND * HIDD];
__device__ __half g_w2h[HIDD * FFND], g_w2l[HIDD * FFND];

// ---------------- small helpers ----------------
__device__ __forceinline__ void red_add_v4(float* p, float a, float b, float c, float d) {
    asm volatile("red.global.add.v4.f32 [%0], {%1,%2,%3,%4};"
                 :: "l"(p), "f"(a), "f"(b), "f"(c), "f"(d) : "memory");
}
__device__ __forceinline__ uint32_t smem_u32(const void* p) {
    uint32_t a;
    asm("{ .reg .u64 t; cvta.to.shared.u64 t, %1; cvt.u32.u64 %0, t; }" : "=r"(a) : "l"(p));
    return a;
}
__device__ __forceinline__ void ldsm4(uint32_t* r, uint32_t addr) {
    asm volatile("ldmatrix.sync.aligned.m8n8.x4.shared.b16 {%0,%1,%2,%3}, [%4];"
                 : "=r"(r[0]), "=r"(r[1]), "=r"(r[2]), "=r"(r[3]) : "r"(addr));
}
__device__ __forceinline__ void mma16816(float* c, const uint32_t* a, const uint32_t* b) {
    asm volatile(
        "mma.sync.aligned.m16n8k16.row.col.f32.f16.f16.f32 "
        "{%0,%1,%2,%3}, {%4,%5,%6,%7}, {%8,%9}, {%0,%1,%2,%3};"
        : "+f"(c[0]), "+f"(c[1]), "+f"(c[2]), "+f"(c[3])
        : "r"(a[0]), "r"(a[1]), "r"(a[2]), "r"(a[3]), "r"(b[0]), "r"(b[1]));
}
__device__ __forceinline__ void cp16(uint32_t dst, const void* src, int pred_bytes) {
    asm volatile("cp.async.cg.shared.global [%0], [%1], 16, %2;"
                 :: "r"(dst), "l"(src), "r"(pred_bytes) : "memory");
}

// SMEM stage: A(128x32 fp16, 80B pitch)=10240, Bh=10240, Bl=10240 -> 30720/stage, x2
#define ROWPITCH 80
#define MAT_BYTES 10240
#define STAGE_BYTES 30720
#define GEMM_SMEM (2 * STAGE_BYTES)

// ---------------- tensor-core GEMM (mma.sync fp16, 2-pass: A*(Bh+Bl)) ----------------
// EPI: 0 f32 store + fused src att dots; 1 bias+gelu -> fp16; 2 bias -> f32
template<int EPI>
__global__ void __launch_bounds__(256, 2) gemm_tc(
    const __half* __restrict__ A,
    const __half* __restrict__ Bh, const __half* __restrict__ Bl,
    float* __restrict__ Cf, __half* __restrict__ Ch,
    const float* __restrict__ bias, const float* __restrict__ att, float* __restrict__ sd,
    int M, int Nd, int Kt)
{
    extern __shared__ __align__(128) char smem[];
    const uint32_t sb = smem_u32(smem);
    const int tid = threadIdx.x, wid = tid >> 5, lane = tid & 31;
    const int bm = blockIdx.y * 128, bn = blockIdx.x * 128;
    const int wm = (wid & 1) * 64, wn = (wid >> 1) * 32;

    float acc[4][4][4];
#pragma unroll
    for (int a = 0; a < 4; a++)
#pragma unroll
        for (int b = 0; b < 4; b++)
#pragma unroll
            for (int q = 0; q < 4; q++) acc[a][b][q] = 0.f;

    const int NC = Kt >> 5;

    auto issue_stage = [&](int c) {
        const int k0 = c << 5;
        const uint32_t stb = sb + (c & 1) * STAGE_BYTES;
#pragma unroll
        for (int j = 0; j < 6; j++) {
            int i = tid + (j << 8);              // 0..1535
            int mt = i >> 9;                     // 0 A, 1 Bh, 2 Bl
            int rem = i & 511;
            int row = rem >> 2, ch = rem & 3;
            uint32_t dst = stb + mt * MAT_BYTES + row * ROWPITCH + ch * 16;
            const __half* src;
            int pb = 16;
            if (mt == 0) {
                int gm = bm + row;
                if (gm >= M) { gm = 0; pb = 0; }
                src = A + (size_t)gm * Kt + k0 + ch * 8;
            } else if (mt == 1) {
                src = Bh + (size_t)(bn + row) * Kt + k0 + ch * 8;
            } else {
                src = Bl + (size_t)(bn + row) * Kt + k0 + ch * 8;
            }
            cp16(dst, src, pb);
        }
        asm volatile("cp.async.commit_group;" ::: "memory");
    };

    issue_stage(0);
    for (int c = 0; c < NC; c++) {
        if (c + 1 < NC) {
            issue_stage(c + 1);
            asm volatile("cp.async.wait_group 1;" ::: "memory");
        } else {
            asm volatile("cp.async.wait_group 0;" ::: "memory");
        }
        __syncthreads();
        const uint32_t stb = sb + (c & 1) * STAGE_BYTES;
#pragma unroll
        for (int kk = 0; kk < 2; kk++) {
            uint32_t bH[2][4], bL[2][4];
            const int brow = wn + (lane & 7) + ((lane >> 4) << 3);
            const int bcol = kk * 32 + ((lane >> 3) & 1) * 16;
#pragma unroll
            for (int p = 0; p < 2; p++) {
                uint32_t bd = stb + MAT_BYTES + (brow + p * 16) * ROWPITCH + bcol;
                ldsm4(bH[p], bd);
                ldsm4(bL[p], bd + MAT_BYTES);
            }
            const int arow = wm + (lane & 15);
            const int acol = kk * 32 + (lane >> 4) * 16;
            uint32_t aF[4][4];
#pragma unroll
            for (int tm = 0; tm < 4; tm++)
                ldsm4(aF[tm], stb + (arow + tm * 16) * ROWPITCH + acol);
#pragma unroll
            for (int tm = 0; tm < 4; tm++)
#pragma unroll
                for (int tn = 0; tn < 4; tn++)
                    mma16816(acc[tm][tn], aF[tm], &bH[tn >> 1][(tn & 1) * 2]);
#pragma unroll
            for (int tm = 0; tm < 4; tm++)
#pragma unroll
                for (int tn = 0; tn < 4; tn++)
                    mma16816(acc[tm][tn], aF[tm], &bL[tn >> 1][(tn & 1) * 2]);
        }
        __syncthreads();
    }

    const int r0 = lane >> 2, c0 = (lane & 3) * 2;

    // fused src att dots (EPI 0): this warp's 32 cols = one head
    if (EPI == 0) {
        const int h = ((bn + wn) >> 5) & 7;
        const float* at0 = att + h * 32;         // t = 0
        const float* at1 = att + 256 + h * 32;   // t = 1
        float dt0[8], dt1[8];
#pragma unroll
        for (int q = 0; q < 8; q++) { dt0[q] = 0.f; dt1[q] = 0.f; }
#pragma unroll
        for (int tn = 0; tn < 4; tn++)
#pragma unroll
            for (int j = 0; j < 2; j++) {
                int cidx = tn * 8 + c0 + j;
                float a0 = at0[cidx], a1 = at1[cidx];
#pragma unroll
                for (int tm = 0; tm < 4; tm++)
#pragma unroll
                    for (int hf = 0; hf < 2; hf++) {
                        float v = acc[tm][tn][hf * 2 + j];
                        dt0[tm * 2 + hf] += v * a0;
                        dt1[tm * 2 + hf] += v * a1;
                    }
            }
#pragma unroll
        for (int q = 0; q < 8; q++) {
            dt0[q] += __shfl_xor_sync(0xffffffffu, dt0[q], 1);
            dt0[q] += __shfl_xor_sync(0xffffffffu, dt0[q], 2);
            dt1[q] += __shfl_xor_sync(0xffffffffu, dt1[q], 1);
            dt1[q] += __shfl_xor_sync(0xffffffffu, dt1[q], 2);
        }
        if ((lane & 3) == 0) {
#pragma unroll
            for (int tm = 0; tm < 4; tm++)
#pragma unroll
                for (int hf = 0; hf < 2; hf++) {
                    int m = bm + wm + tm * 16 + hf * 8 + r0;
                    if (m < M) {
                        sd[m * 16 + h]     = dt0[tm * 2 + hf];
                        sd[m * 16 + 8 + h] = dt1[tm * 2 + hf];
                    }
                }
        }
    }

    // epilogue stores
#pragma unroll
    for (int tm = 0; tm < 4; tm++) {
        const int mbase = bm + wm + tm * 16 + r0;
#pragma unroll
        for (int tn = 0; tn < 4; tn++) {
            const int n0 = bn + wn + tn * 8 + c0;
#pragma unroll
            for (int hf = 0; hf < 2; hf++) {
                const int m = mbase + hf * 8;
                if (m >= M) continue;
                float v0 = acc[tm][tn][hf * 2];
                float v1 = acc[tm][tn][hf * 2 + 1];
                if (EPI == 0) {
                    *(float2*)(Cf + (size_t)m * Nd + n0) = make_float2(v0, v1);
                } else if (EPI == 2) {
                    v0 += bias[n0]; v1 += bias[n0 + 1];
                    *(float2*)(Cf + (size_t)m * Nd + n0) = make_float2(v0, v1);
                } else {
                    v0 += bias[n0]; v1 += bias[n0 + 1];
                    v0 = 0.5f * v0 * (1.f + erff(v0 * 0.70710678118654752f));
                    v1 = 0.5f * v1 * (1.f + erff(v1 * 0.70710678118654752f));
                    __half2 hp; hp.x = __float2half(v0); hp.y = __float2half(v1);
                    *(__half2*)(Ch + (size_t)m * Nd + n0) = hp;
                }
            }
        }
    }
}

// ---------------- dst att dots (V built in-CTA; src dots fused in gemm0) -------
__global__ void __launch_bounds__(256) dots_kernel(const float* __restrict__ x,
                                                   const float* __restrict__ Wdst,
                                                   const float* __restrict__ att_dst) {
    __shared__ float sVt[256][16];   // Vdst^T — 16KB
    int tid = threadIdx.x;
    {
        float a16[16];
#pragma unroll
        for (int q = 0; q < 16; q++) a16[q] = 0.f;
        for (int c = 0; c < 32; c++) {
#pragma unroll
            for (int h = 0; h < 8; h++) {
                float wv = Wdst[(h * 32 + c) * 256 + tid];
                a16[h]     += wv * __ldg(&att_dst[h * 32 + c]);
                a16[8 + h] += wv * __ldg(&att_dst[(8 + h) * 32 + c]);
            }
        }
#pragma unroll
        for (int q = 0; q < 16; q++) sVt[tid][q] = a16[q];
    }
    __syncthreads();
    int lane = tid & 31;
    int half = lane >> 4;
    int j = lane & 15;
    int gw = (blockIdx.x * 256 + tid) >> 5;
    int nw = (gridDim.x * 256) >> 5;
    for (int nb = gw * 8; nb < NN; nb += nw * 8) {
        int m0 = nb + half * 4;
        int m1 = m0 + 1, m2 = m0 + 2, m3 = m0 + 3;
        bool ok0 = m0 < NN, ok1 = m1 < NN, ok2 = m2 < NN, ok3 = m3 < NN;
        const float4* x0 = (const float4*)&x[(size_t)(ok0 ? m0 : 0) * HIDD];
        const float4* x1 = (const float4*)&x[(size_t)(ok1 ? m1 : 0) * HIDD];
        const float4* x2 = (const float4*)&x[(size_t)(ok2 ? m2 : 0) * HIDD];
        const float4* x3 = (const float4*)&x[(size_t)(ok3 ? m3 : 0) * HIDD];
        float a0 = 0.f, a1 = 0.f, a2 = 0.f, a3 = 0.f;
#pragma unroll 2
        for (int k4 = 0; k4 < 64; k4++) {
            float s0 = sVt[k4 * 4 + 0][j];
            float s1 = sVt[k4 * 4 + 1][j];
            float s2 = sVt[k4 * 4 + 2][j];
            float s3 = sVt[k4 * 4 + 3][j];
            float4 v;
            v = x0[k4]; a0 += v.x * s0 + v.y * s1 + v.z * s2 + v.w * s3;
            v = x1[k4]; a1 += v.x * s0 + v.y * s1 + v.z * s2 + v.w * s3;
            v = x2[k4]; a2 += v.x * s0 + v.y * s1 + v.z * s2 + v.w * s3;
            v = x3[k4]; a3 += v.x * s0 + v.y * s1 + v.z * s2 + v.w * s3;
        }
        if (ok0) g_sdst[m0 * 16 + j] = a0;
        if (ok1) g_sdst[m1 * 16 + j] = a1;
        if (ok2) g_sdst[m2 * 16 + j] = a2;
        if (ok3) g_sdst[m3 * 16 + j] = a3;
    }
}

// ---------------- prep: fp16 conversions + zero agg/denom ----------------
#define SPLIT_X_N4   (NN * HIDD / 4)
#define SPLIT_WS_N4  (HIDD * HIDD / 4)
#define SPLIT_W1_N4  (FFND * HIDD / 4)
#define SPLIT_W2_N4  (HIDD * FFND / 4)
#define SPLIT_TOTAL  (SPLIT_X_N4 + SPLIT_WS_N4 + SPLIT_W1_N4 + SPLIT_W2_N4)

__global__ void prep_kernel(const float* __restrict__ x, const float* __restrict__ Wsrc,
                            const float* __restrict__ W1, const float* __restrict__ W2) {
    int i = blockIdx.x * blockDim.x + threadIdx.x;
    if (i >= SPLIT_TOTAL) return;
    if (i < SPLIT_X_N4)
        *(float4*)(g_agg + (size_t)i * 4) = make_float4(0.f, 0.f, 0.f, 0.f);
    if (i < NN * 2)
        *(float4*)(g_denom + (size_t)i * 4) = make_float4(0.f, 0.f, 0.f, 0.f);
    if (i < SPLIT_X_N4) {
        // activations: single fp16
        float4 v = *(const float4*)(x + (size_t)i * 4);
        __half2 p0; p0.x = __float2half(v.x); p0.y = __float2half(v.y);
        __half2 p1; p1.x = __float2half(v.z); p1.y = __float2half(v.w);
        *(__half2*)(g_xa + (size_t)i * 4)     = p0;
        *(__half2*)(g_xa + (size_t)i * 4 + 2) = p1;
        return;
    }
    // weights: fp16 hi/lo split
    const float* in; __half *hi, *lo; int off;
    if (i < SPLIT_X_N4 + SPLIT_WS_N4) {
        in = Wsrc; hi = g_wsh; lo = g_wsl; off = i - SPLIT_X_N4;
    } else if (i < SPLIT_X_N4 + SPLIT_WS_N4 + SPLIT_W1_N4) {
        in = W1; hi = g_w1h; lo = g_w1l; off = i - SPLIT_X_N4 - SPLIT_WS_N4;
    } else {
        in = W2; hi = g_w2h; lo = g_w2l; off = i - SPLIT_X_N4 - SPLIT_WS_N4 - SPLIT_W1_N4;
    }
    float4 v = *(const float4*)(in + (size_t)off * 4);
    __half h0 = __float2half(v.x), h1 = __float2half(v.y);
    __half h2 = __float2half(v.z), h3 = __float2half(v.w);
    __half2 hp0; hp0.x = h0; hp0.y = h1;
    __half2 hp1; hp1.x = h2; hp1.y = h3;
    __half2 lp0, lp1;
    lp0.x = __float2half(v.x - __half2float(h0));
    lp0.y = __float2half(v.y - __half2float(h1));
    lp1.x = __float2half(v.z - __half2float(h2));
    lp1.y = __float2half(v.w - __half2float(h3));
    *(__half2*)(hi + (size_t)off * 4)     = hp0;
    *(__half2*)(hi + (size_t)off * 4 + 2) = hp1;
    *(__half2*)(lo + (size_t)off * 4)     = lp0;
    *(__half2*)(lo + (size_t)off * 4 + 2) = lp1;
}

// ---------------- fused edge pass: alpha -> leaky -> exp -> denom + scatter ----------
__global__ void __launch_bounds__(256) edge_fused(const int* __restrict__ ei,
                                                  const int* __restrict__ et,
                                                  const float* __restrict__ ew) {
    int e = (blockIdx.x * blockDim.x + threadIdx.x) >> 5;
    int lane = threadIdx.x & 31;
    if (e >= ETOT) return;
    int s, d, t; float w;
    if (e < EE) { s = ei[e]; d = ei[EE + e]; t = et[e]; w = ew[e]; }
    else        { s = d = e - EE; t = 0; w = 1.f; }
    float cv = 0.f;
    if (lane < 8) {
        float a = g_ssrc[s * 16 + t * 8 + lane] + g_sdst[d * 16 + t * 8 + lane];
        a = (a >= 0.f) ? a : 0.2f * a;
        float p = __expf(a);
        atomicAdd(&g_denom[d * 8 + lane], p);
        cv = p * w;
    }
    float c1 = __shfl_sync(0xffffffffu, cv, lane >> 3);        // heads 0..3
    float c2 = __shfl_sync(0xffffffffu, cv, 4 + (lane >> 3));  // heads 4..7
    const float4* xs = (const float4*)&g_xsrc[(size_t)s * HIDD];
    float4 v1 = xs[lane];
    float4 v2 = xs[32 + lane];
    float* op = &g_agg[(size_t)d * HIDD];
    red_add_v4(op + lane * 4,       v1.x * c1, v1.y * c1, v1.z * c1, v1.w * c1);
    red_add_v4(op + 128 + lane * 4, v2.x * c2, v2.y * c2, v2.z * c2, v2.w * c2);
}

// ---------------- LayerNorm: out = LN(a[/denom] + b + colbias?), optional fp16 out ----
__global__ void ln_kernel(const float* __restrict__ a, const float* __restrict__ b,
                          const float* __restrict__ colbias, const float* __restrict__ denom,
                          const float* __restrict__ g, const float* __restrict__ beta,
                          float* __restrict__ out, __half* __restrict__ ohf) {
    int row = (blockIdx.x * blockDim.x + threadIdx.x) >> 5;
    int lane = threadIdx.x & 31;
    if (row >= NN) return;
    size_t base = (size_t)row * HIDD;
    float4 a0 = *(const float4*)&a[base + lane * 4];
    float4 a1 = *(const float4*)&a[base + 128 + lane * 4];
    float4 b0 = *(const float4*)&b[base + lane * 4];
    float4 b1 = *(const float4*)&b[base + 128 + lane * 4];
    if (denom) {
        float r0 = __frcp_rn(denom[row * 8 + (lane >> 3)]);
        float r1 = __frcp_rn(denom[row * 8 + 4 + (lane >> 3)]);
        a0.x *= r0; a0.y *= r0; a0.z *= r0; a0.w *= r0;
        a1.x *= r1; a1.y *= r1; a1.z *= r1; a1.w *= r1;
    }
    float v[8] = { a0.x + b0.x, a0.y + b0.y, a0.z + b0.z, a0.w + b0.w,
                   a1.x + b1.x, a1.y + b1.y, a1.z + b1.z, a1.w + b1.w };
    if (colbias) {
        float4 c0 = *(const float4*)&colbias[lane * 4];
        float4 c1 = *(const float4*)&colbias[128 + lane * 4];
        v[0] += c0.x; v[1] += c0.y; v[2] += c0.z; v[3] += c0.w;
        v[4] += c1.x; v[5] += c1.y; v[6] += c1.z; v[7] += c1.w;
    }
    float s = 0.f, s2 = 0.f;
#pragma unroll
    for (int q = 0; q < 8; q++) { s += v[q]; s2 += v[q] * v[q]; }
#pragma unroll
    for (int off = 16; off; off >>= 1) {
        s  += __shfl_xor_sync(0xffffffffu, s, off);
        s2 += __shfl_xor_sync(0xffffffffu, s2, off);
    }
    float mu = s * (1.f / 256.f);
    float var = s2 * (1.f / 256.f) - mu * mu;
    float r = rsqrtf(var + 1e-5f);
    float4 g0 = *(const float4*)&g[lane * 4];
    float4 g1 = *(const float4*)&g[128 + lane * 4];
    float4 e0 = *(const float4*)&beta[lane * 4];
    float4 e1 = *(const float4*)&beta[128 + lane * 4];
    float o[8];
    o[0] = (v[0] - mu) * r * g0.x + e0.x; o[1] = (v[1] - mu) * r * g0.y + e0.y;
    o[2] = (v[2] - mu) * r * g0.z + e0.z; o[3] = (v[3] - mu) * r * g0.w + e0.w;
    o[4] = (v[4] - mu) * r * g1.x + e1.x; o[5] = (v[5] - mu) * r * g1.y + e1.y;
    o[6] = (v[6] - mu) * r * g1.z + e1.z; o[7] = (v[7] - mu) * r * g1.w + e1.w;
    *(float4*)&out[base + lane * 4]       = make_float4(o[0], o[1], o[2], o[3]);
    *(float4*)&out[base + 128 + lane * 4] = make_float4(o[4], o[5], o[6], o[7]);
    if (ohf) {
#pragma unroll
        for (int q = 0; q < 8; q += 2) {
            int col = (q < 4) ? (lane * 4 + q) : (128 + lane * 4 + q - 4);
            __half2 hp; hp.x = __float2half(o[q]); hp.y = __float2half(o[q + 1]);
            *(__half2*)(ohf + base + col) = hp;
        }
    }
}

// ---------------- launch ----------------
extern "C" void kernel_launch(void* const* d_in, const int* in_sizes, int n_in,
                              void* d_out, int out_size) {
    const float* x       = (const float*)d_in[0];
    const int*   ei      = (const int*)  d_in[1];
    const int*   et      = (const int*)  d_in[2];
    const float* ew      = (const float*)d_in[3];
    const float* Wsrc    = (const float*)d_in[4];
    const float* Wdst    = (const float*)d_in[5];
    const float* att_src = (const float*)d_in[6];
    const float* att_dst = (const float*)d_in[7];
    const float* bias    = (const float*)d_in[8];
    const float* ln1g    = (const float*)d_in[9];
    const float* ln1b    = (const float*)d_in[10];
    const float* ln2g    = (const float*)d_in[11];
    const float* ln2b    = (const float*)d_in[12];
    const float* W1      = (const float*)d_in[13];
    const float* b1      = (const float*)d_in[14];
    const float* W2      = (const float*)d_in[15];
    const float* b2      = (const float*)d_in[16];
    float* out = (float*)d_out;

    float *p_xsrc, *p_h, *p_agg, *p_denom, *p_ssrc;
    cudaGetSymbolAddress((void**)&p_xsrc, g_xsrc);
    cudaGetSymbolAddress((void**)&p_h,    g_h);
    cudaGetSymbolAddress((void**)&p_agg,  g_agg);
    cudaGetSymbolAddress((void**)&p_denom, g_denom);
    cudaGetSymbolAddress((void**)&p_ssrc, g_ssrc);
    __half *p_xa, *p_ha, *p_ma;
    __half *p_wsh, *p_wsl, *p_w1h, *p_w1l, *p_w2h, *p_w2l;
    cudaGetSymbolAddress((void**)&p_xa, g_xa);
    cudaGetSymbolAddress((void**)&p_ha, g_ha);
    cudaGetSymbolAddress((void**)&p_ma, g_ma);
    cudaGetSymbolAddress((void**)&p_wsh, g_wsh); cudaGetSymbolAddress((void**)&p_wsl, g_wsl);
    cudaGetSymbolAddress((void**)&p_w1h, g_w1h); cudaGetSymbolAddress((void**)&p_w1l, g_w1l);
    cudaGetSymbolAddress((void**)&p_w2h, g_w2h); cudaGetSymbolAddress((void**)&p_w2l, g_w2l);

    cudaFuncSetAttribute(gemm_tc<0>, cudaFuncAttributeMaxDynamicSharedMemorySize, GEMM_SMEM);
    cudaFuncSetAttribute(gemm_tc<1>, cudaFuncAttributeMaxDynamicSharedMemorySize, GEMM_SMEM);
    cudaFuncSetAttribute(gemm_tc<2>, cudaFuncAttributeMaxDynamicSharedMemorySize, GEMM_SMEM);

    const int TPB = 256;
    prep_kernel<<<(SPLIT_TOTAL + TPB - 1) / TPB, TPB>>>(x, Wsrc, W1, W2);     // 1
    dots_kernel<<<296, 256>>>(x, Wdst, att_dst);                              // 2
    // xsrc = x @ Wsrc^T + fused src att dots                                  // 3
    gemm_tc<0><<<dim3(HIDD / 128, MTILES), 256, GEMM_SMEM>>>(
        p_xa, p_wsh, p_wsl, p_xsrc, nullptr, nullptr, att_src, p_ssrc,
        NN, HIDD, HIDD);
    edge_fused<<<((size_t)ETOT * 32 + TPB - 1) / TPB, TPB>>>(ei, et, ew);     // 4

    // h = LN1(agg/denom + bias + x), fused fp16 output for FFN input
    ln_kernel<<<(NN * 32 + TPB - 1) / TPB, TPB>>>(p_agg, x, bias, p_denom,
                                                  ln1g, ln1b, p_h, p_ha);

    // FFN1: mid = gelu(h @ W1^T + b1) -> fp16
    gemm_tc<1><<<dim3(FFND / 128, MTILES), 256, GEMM_SMEM>>>(
        p_ha, p_w1h, p_w1l, nullptr, p_ma, b1, nullptr, nullptr,
        NN, FFND, HIDD);
    // FFN2: agg = mid @ W2^T + b2
    gemm_tc<2><<<dim3(HIDD / 128, MTILES), 256, GEMM_SMEM>>>(
        p_ma, p_w2h, p_w2l, p_agg, nullptr, b2, nullptr, nullptr,
        NN, HIDD, FFND);

    // out = LN2(h + ffn_out)
    ln_kernel<<<(NN * 32 + TPB - 1) / TPB, TPB>>>(p_agg, p_h, nullptr, nullptr,
                                                  ln2g, ln2b, out, nullptr);
}